// round 1
// baseline (speedup 1.0000x reference)
#include <cuda_runtime.h>
#include <cuda_bf16.h>
#include <math.h>

// Problem constants
#define BB 4
#define SS 2048
#define EE 1024
#define HH 16
#define DD 64
#define MM (BB * SS)   // 8192 rows for all big GEMMs
#define NN 1024
#define KK 1024

// Scratch (device globals — allowed; no cudaMalloc)
__device__ float g_q[BB * HH * SS * DD];    // [b][h][s][d]
__device__ float g_k[BB * HH * SS * DD];
__device__ float g_v[BB * HH * SS * DD];
__device__ float g_attn[MM * EE];           // [b][s][h*64+d]

// ---------------------------------------------------------------------------
// SGEMM: out[M=8192, N=1024] = A[8192,1024] * W + bias
// mode 0: W is [K,N] row-major, out row-major [M,N]
// mode 1: W is [H,E,D] (per-head), out is [B,H,S,D]
// Tiles: BM=128, BN=128, BK=16; 256 threads, 8x8 per-thread micro tile (split 2x2 of 4x4)
// ---------------------------------------------------------------------------
__global__ void __launch_bounds__(256) sgemm_kernel(
    const float* __restrict__ A, const float* __restrict__ W,
    const float* __restrict__ bias, float* __restrict__ out, int mode)
{
    __shared__ float Ast[16][128];  // transposed A tile: [k][m]
    __shared__ float Bs[16][128];   // [k][n]

    const int tid = threadIdx.x;
    const int tx = tid & 15;
    const int ty = tid >> 4;
    const int bm = blockIdx.y * 128;
    const int bn = blockIdx.x * 128;

    // global load mapping
    const int arow = tid >> 1;            // 0..127
    const int akq  = (tid & 1) * 8;       // k offset 0 or 8
    const int brow = tid >> 4;            // k 0..15
    const int bcol = (tid & 15) * 8;      // n offset, 8-wide

    float acc[2][2][4][4];
#pragma unroll
    for (int a = 0; a < 2; a++)
#pragma unroll
        for (int b = 0; b < 2; b++)
#pragma unroll
            for (int i = 0; i < 4; i++)
#pragma unroll
                for (int j = 0; j < 4; j++) acc[a][b][i][j] = 0.f;

    const float* arow_ptr = A + (size_t)(bm + arow) * KK;

    for (int k0 = 0; k0 < KK; k0 += 16) {
        // issue global loads
        float4 a0 = *(const float4*)(arow_ptr + k0 + akq);
        float4 a1 = *(const float4*)(arow_ptr + k0 + akq + 4);
        float4 b0, b1;
        if (mode == 1) {
            int n = bn + bcol;
            int h = n >> 6;
            int d = n & 63;
            const float* wp = W + ((size_t)h * EE + (k0 + brow)) * DD + d;
            b0 = *(const float4*)(wp);
            b1 = *(const float4*)(wp + 4);
        } else {
            const float* wp = W + (size_t)(k0 + brow) * NN + bn + bcol;
            b0 = *(const float4*)(wp);
            b1 = *(const float4*)(wp + 4);
        }
        __syncthreads();  // previous iteration's smem reads done
        // store A transposed
        Ast[akq + 0][arow] = a0.x; Ast[akq + 1][arow] = a0.y;
        Ast[akq + 2][arow] = a0.z; Ast[akq + 3][arow] = a0.w;
        Ast[akq + 4][arow] = a1.x; Ast[akq + 5][arow] = a1.y;
        Ast[akq + 6][arow] = a1.z; Ast[akq + 7][arow] = a1.w;
        *(float4*)&Bs[brow][bcol]     = b0;
        *(float4*)&Bs[brow][bcol + 4] = b1;
        __syncthreads();
#pragma unroll
        for (int kk = 0; kk < 16; ++kk) {
            float4 af0 = *(const float4*)&Ast[kk][ty * 4];
            float4 af1 = *(const float4*)&Ast[kk][64 + ty * 4];
            float4 bf0 = *(const float4*)&Bs[kk][tx * 4];
            float4 bf1 = *(const float4*)&Bs[kk][64 + tx * 4];
            float av[2][4] = {{af0.x, af0.y, af0.z, af0.w}, {af1.x, af1.y, af1.z, af1.w}};
            float bv[2][4] = {{bf0.x, bf0.y, bf0.z, bf0.w}, {bf1.x, bf1.y, bf1.z, bf1.w}};
#pragma unroll
            for (int ri = 0; ri < 2; ri++)
#pragma unroll
                for (int i = 0; i < 4; i++)
#pragma unroll
                    for (int ci = 0; ci < 2; ci++)
#pragma unroll
                        for (int j = 0; j < 4; j++)
                            acc[ri][ci][i][j] += av[ri][i] * bv[ci][j];
        }
    }

    // epilogue
#pragma unroll
    for (int ri = 0; ri < 2; ri++) {
#pragma unroll
        for (int i = 0; i < 4; i++) {
            int row = bm + ri * 64 + ty * 4 + i;   // m index
            int b = row >> 11;                      // row / 2048
            int s = row & 2047;
#pragma unroll
            for (int ci = 0; ci < 2; ci++) {
#pragma unroll
                for (int j = 0; j < 4; j++) {
                    int col = bn + ci * 64 + tx * 4 + j;
                    float val = acc[ri][ci][i][j] + bias[col];
                    if (mode == 1) {
                        int h = col >> 6;
                        int d = col & 63;
                        out[(((size_t)b * HH + h) * SS + s) * DD + d] = val;
                    } else {
                        out[(size_t)row * NN + col] = val;
                    }
                }
            }
        }
    }
}

// ---------------------------------------------------------------------------
// Flash attention (causal), fp32, Br=Bc=64.
// grid: (S/64, B*H); 256 threads (8 warps); warp w owns local rows w*8..w*8+7,
// lane l owns columns {l, l+32} of both the score tile and the output tile.
// ---------------------------------------------------------------------------
#define FLDS 68  // smem row stride (words) — conflict-free for row-major lane access

__global__ void __launch_bounds__(256) flash_kernel(
    const float* __restrict__ q, const float* __restrict__ k,
    const float* __restrict__ v, float* __restrict__ outp)
{
    extern __shared__ float sm[];
    float* Qs = sm;                 // [64][FLDS]   Q tile [r][d]
    float* KP = sm + 64 * FLDS;     // K tile [t][d], then P tile [r][t]
    float* Vt = sm + 2 * 64 * FLDS; // V transposed [d][t]

    const int qi = blockIdx.x;
    const int bh = blockIdx.y;
    const size_t base = (size_t)bh * SS * DD;
    const int tid = threadIdx.x;
    const int w = tid >> 5;
    const int l = tid & 31;
    const int r0 = w * 8;          // local row base
    const int qr0 = qi * 64;       // global query row base

    // load Q tile
    for (int idx = tid; idx < 64 * 16; idx += 256) {
        int r = idx >> 4;
        int dq = (idx & 15) * 4;
        *(float4*)&Qs[r * FLDS + dq] = *(const float4*)(q + base + (size_t)(qr0 + r) * DD + dq);
    }

    float m_run[8], l_run[8], o[8][2];
#pragma unroll
    for (int i = 0; i < 8; i++) {
        m_run[i] = -1e30f; l_run[i] = 0.f; o[i][0] = 0.f; o[i][1] = 0.f;
    }

    const float sc = 0.125f * 1.4426950408889634f;  // D^-0.5 * log2(e)

    for (int j = 0; j <= qi; ++j) {
        __syncthreads();  // done with previous tile's KP(P)/Vt
        // load K tile + V tile (transposed)
        for (int idx = tid; idx < 64 * 16; idx += 256) {
            int t = idx >> 4;
            int dq = (idx & 15) * 4;
            const float* kb = k + base + (size_t)(j * 64 + t) * DD + dq;
            *(float4*)&KP[t * FLDS + dq] = *(const float4*)kb;
            float4 vv = *(const float4*)(v + base + (size_t)(j * 64 + t) * DD + dq);
            Vt[(dq + 0) * FLDS + t] = vv.x;
            Vt[(dq + 1) * FLDS + t] = vv.y;
            Vt[(dq + 2) * FLDS + t] = vv.z;
            Vt[(dq + 3) * FLDS + t] = vv.w;
        }
        __syncthreads();

        // S = Q K^T for this warp's 8 rows, lane's 2 key columns
        float s[8][2];
#pragma unroll
        for (int i = 0; i < 8; i++) { s[i][0] = 0.f; s[i][1] = 0.f; }
#pragma unroll
        for (int d4 = 0; d4 < 64; d4 += 4) {
            float4 k0f = *(const float4*)&KP[l * FLDS + d4];
            float4 k1f = *(const float4*)&KP[(l + 32) * FLDS + d4];
#pragma unroll
            for (int i = 0; i < 8; i++) {
                float4 qf = *(const float4*)&Qs[(r0 + i) * FLDS + d4];
                s[i][0] += qf.x * k0f.x + qf.y * k0f.y + qf.z * k0f.z + qf.w * k0f.w;
                s[i][1] += qf.x * k1f.x + qf.y * k1f.y + qf.z * k1f.z + qf.w * k1f.w;
            }
        }

        const bool diag = (j == qi);
#pragma unroll
        for (int i = 0; i < 8; i++) {
            float s0 = s[i][0] * sc;
            float s1 = s[i][1] * sc;
            if (diag) {
                int R = r0 + i;  // local row == local key bound on diagonal tile
                if (l > R) s0 = -1e30f;
                if (l + 32 > R) s1 = -1e30f;
            }
            float mloc = fmaxf(s0, s1);
#pragma unroll
            for (int off = 16; off; off >>= 1)
                mloc = fmaxf(mloc, __shfl_xor_sync(0xffffffffu, mloc, off));
            float mn = fmaxf(m_run[i], mloc);
            float p0 = exp2f(s0 - mn);
            float p1 = exp2f(s1 - mn);
            float alpha = exp2f(m_run[i] - mn);
            float rs = p0 + p1;
#pragma unroll
            for (int off = 16; off; off >>= 1)
                rs += __shfl_xor_sync(0xffffffffu, rs, off);
            l_run[i] = l_run[i] * alpha + rs;
            m_run[i] = mn;
            o[i][0] *= alpha;
            o[i][1] *= alpha;
            s[i][0] = p0;
            s[i][1] = p1;
        }

        __syncthreads();  // all warps done reading K from KP
        // stage P over the K buffer: P[r][t]
#pragma unroll
        for (int i = 0; i < 8; i++) {
            KP[(r0 + i) * FLDS + l]      = s[i][0];
            KP[(r0 + i) * FLDS + l + 32] = s[i][1];
        }
        __syncthreads();

        // O += P V ; lane owns output cols {l, l+32}
#pragma unroll
        for (int t4 = 0; t4 < 64; t4 += 4) {
            float4 v0f = *(const float4*)&Vt[l * FLDS + t4];
            float4 v1f = *(const float4*)&Vt[(l + 32) * FLDS + t4];
#pragma unroll
            for (int i = 0; i < 8; i++) {
                float4 pf = *(const float4*)&KP[(r0 + i) * FLDS + t4];
                o[i][0] += pf.x * v0f.x + pf.y * v0f.y + pf.z * v0f.z + pf.w * v0f.w;
                o[i][1] += pf.x * v1f.x + pf.y * v1f.y + pf.z * v1f.z + pf.w * v1f.w;
            }
        }
    }

    // epilogue: normalize and write to [B, S, H*D]
    const int b = bh >> 4;
    const int h = bh & 15;
#pragma unroll
    for (int i = 0; i < 8; i++) {
        int R = qr0 + r0 + i;
        float inv = 1.f / l_run[i];
        size_t ob = ((size_t)b * SS + R) * EE + h * 64;
        outp[ob + l]      = o[i][0] * inv;
        outp[ob + l + 32] = o[i][1] * inv;
    }
}

// ---------------------------------------------------------------------------
extern "C" void kernel_launch(void* const* d_in, const int* in_sizes, int n_in,
                              void* d_out, int out_size)
{
    const float* x  = (const float*)d_in[0];
    const float* Wq = (const float*)d_in[1];
    const float* bq = (const float*)d_in[2];
    const float* Wk = (const float*)d_in[3];
    const float* bk = (const float*)d_in[4];
    const float* Wv = (const float*)d_in[5];
    const float* bv = (const float*)d_in[6];
    const float* Wp = (const float*)d_in[7];
    const float* bp = (const float*)d_in[8];
    float* out = (float*)d_out;

    float *qp, *kp, *vp, *ap;
    cudaGetSymbolAddress((void**)&qp, g_q);
    cudaGetSymbolAddress((void**)&kp, g_k);
    cudaGetSymbolAddress((void**)&vp, g_v);
    cudaGetSymbolAddress((void**)&ap, g_attn);

    const int fl_smem = 3 * 64 * FLDS * sizeof(float);  // 52224 B
    cudaFuncSetAttribute(flash_kernel, cudaFuncAttributeMaxDynamicSharedMemorySize, fl_smem);

    dim3 gg(NN / 128, MM / 128);   // (8, 64)
    sgemm_kernel<<<gg, 256>>>(x, Wq, bq, qp, 1);
    sgemm_kernel<<<gg, 256>>>(x, Wk, bk, kp, 1);
    sgemm_kernel<<<gg, 256>>>(x, Wv, bv, vp, 1);

    dim3 fg(SS / 64, BB * HH);     // (32, 64)
    flash_kernel<<<fg, 256, fl_smem>>>(qp, kp, vp, ap);

    sgemm_kernel<<<gg, 256>>>(ap, Wp, bp, out, 0);
}

// round 4
// speedup vs baseline: 1.3854x; 1.3854x over previous
#include <cuda_runtime.h>
#include <cuda_bf16.h>
#include <math.h>
#include <cstdint>

// Problem constants
#define BB 4
#define SS 2048
#define EE 1024
#define HH 16
#define DD 64
#define MM (BB * SS)   // 8192
#define NN 1024
#define KK 1024

// Scratch (device globals — no cudaMalloc allowed)
__device__ float g_q[BB * HH * SS * DD];    // [b][h][s][d]
__device__ float g_k[BB * HH * SS * DD];
__device__ float g_v[BB * HH * SS * DD];
__device__ float g_attn[MM * EE];           // [b][s][h*64+d], tf32-rounded
__device__ float g_xa[MM * KK];             // x, tf32-rounded
__device__ float g_wt[NN * KK];             // current weight, transposed [N][K], tf32-rounded

// ---------------------------------------------------------------------------
// helpers (all plain sm_100-target instructions: mma.sync sm_80+, cp.async sm_80+)
// ---------------------------------------------------------------------------
__device__ __forceinline__ uint32_t smem_u32(const void* p) {
    uint32_t a;
    asm("{ .reg .u64 t; cvta.to.shared.u64 t, %1; cvt.u32.u64 %0, t; }" : "=r"(a) : "l"(p));
    return a;
}
__device__ __forceinline__ float tf32r(float x) {
    uint32_t y;
    asm("cvt.rna.tf32.f32 %0, %1;" : "=r"(y) : "f"(x));
    return __uint_as_float(y);
}
__device__ __forceinline__ uint32_t lds32(uint32_t a) {
    uint32_t v;
    asm volatile("ld.shared.b32 %0, [%1];" : "=r"(v) : "r"(a));
    return v;
}
__device__ __forceinline__ void cp16(uint32_t dst, const void* src) {
    asm volatile("cp.async.ca.shared.global [%0], [%1], 16;" :: "r"(dst), "l"(src));
}
__device__ __forceinline__ void mma_tf32(float* c, const uint32_t* a, const uint32_t* b) {
    asm volatile(
        "mma.sync.aligned.m16n8k8.row.col.f32.tf32.tf32.f32 "
        "{%0,%1,%2,%3}, {%4,%5,%6,%7}, {%8,%9}, {%0,%1,%2,%3};"
        : "+f"(c[0]), "+f"(c[1]), "+f"(c[2]), "+f"(c[3])
        : "r"(a[0]), "r"(a[1]), "r"(a[2]), "r"(a[3]), "r"(b[0]), "r"(b[1]));
}

// ---------------------------------------------------------------------------
// mma.sync TF32 GEMM: out[M,N] = A[M,K] * Bt[N,K]^T + bias
// BM=BN=128, BK=16, 256 threads (8 warps, 2x4 warp grid, 64x32 warp tile).
// cp.async 3-stage pipeline. smem row stride = 20 floats (bank-conflict-free).
// mode 1: out is [B,H,S,D] per-head;  mode 0: out row-major [M,N]
// ---------------------------------------------------------------------------
#define GROWB 80                // bytes per smem row (16 data floats + 4 pad)
#define GBUF (128 * GROWB)      // 10240 B, one matrix one stage
#define GSTAGEB (2 * GBUF)      // 20480 B, A+B one stage
#define GNSTG 3
#define GNKS (KK / 16)          // 64 stages

__global__ void __launch_bounds__(256) tc_gemm_kernel(
    const float* __restrict__ A, const float* __restrict__ Bt,
    const float* __restrict__ bias, float* __restrict__ out, int mode)
{
    extern __shared__ char smc[];
    const uint32_t dat_u = smem_u32(smc);

    const int tid = threadIdx.x;
    const int wid = tid >> 5;
    const int lane = tid & 31;
    const int g = lane >> 2;      // group 0..7
    const int t = lane & 3;       // thread-in-group 0..3
    const int wm = wid >> 2;      // 0..1
    const int wn = wid & 3;       // 0..3
    const int bm = blockIdx.y * 128;
    const int bn = blockIdx.x * 128;

    // per-thread global->smem chunks: 2 x 16B per matrix per stage
    const int c0 = tid * 2;

    float acc[4][4][4];
#pragma unroll
    for (int mt = 0; mt < 4; mt++)
#pragma unroll
        for (int nt = 0; nt < 4; nt++)
#pragma unroll
            for (int r = 0; r < 4; r++) acc[mt][nt][r] = 0.f;

    // prologue: prefetch stages 0,1
#pragma unroll
    for (int s = 0; s < GNSTG - 1; ++s) {
        const uint32_t sb = dat_u + s * GSTAGEB;
        const int kof = s * 16;
#pragma unroll
        for (int i = 0; i < 2; ++i) {
            int c = c0 + i;
            int row = c >> 2, q = c & 3;
            cp16(sb + row * GROWB + q * 16, A + (size_t)(bm + row) * KK + kof + q * 4);
            cp16(sb + GBUF + row * GROWB + q * 16, Bt + (size_t)(bn + row) * KK + kof + q * 4);
        }
        asm volatile("cp.async.commit_group;" ::: "memory");
    }

    for (int ks = 0; ks < GNKS; ++ks) {
        const int ldk = ks + GNSTG - 1;
        if (ldk < GNKS) {
            const uint32_t sb = dat_u + (ldk % GNSTG) * GSTAGEB;
            const int kof = ldk * 16;
#pragma unroll
            for (int i = 0; i < 2; ++i) {
                int c = c0 + i;
                int row = c >> 2, q = c & 3;
                cp16(sb + row * GROWB + q * 16, A + (size_t)(bm + row) * KK + kof + q * 4);
                cp16(sb + GBUF + row * GROWB + q * 16, Bt + (size_t)(bn + row) * KK + kof + q * 4);
            }
        }
        asm volatile("cp.async.commit_group;" ::: "memory");
        asm volatile("cp.async.wait_group 2;" ::: "memory");
        __syncthreads();

        const uint32_t aB = dat_u + (ks % GNSTG) * GSTAGEB;
        const uint32_t bB = aB + GBUF;
#pragma unroll
        for (int k2 = 0; k2 < 2; ++k2) {   // two k=8 steps in BK=16
            uint32_t af[4][4], bf[4][2];
#pragma unroll
            for (int mt = 0; mt < 4; mt++) {
                int row = wm * 64 + mt * 16 + g;
                uint32_t a0 = aB + row * GROWB + (k2 * 8 + t) * 4;
                af[mt][0] = lds32(a0);
                af[mt][1] = lds32(a0 + 8 * GROWB);
                af[mt][2] = lds32(a0 + 16);
                af[mt][3] = lds32(a0 + 8 * GROWB + 16);
            }
#pragma unroll
            for (int nt = 0; nt < 4; nt++) {
                int nrow = wn * 32 + nt * 8 + g;
                uint32_t b0 = bB + nrow * GROWB + (k2 * 8 + t) * 4;
                bf[nt][0] = lds32(b0);
                bf[nt][1] = lds32(b0 + 16);
            }
#pragma unroll
            for (int mt = 0; mt < 4; mt++)
#pragma unroll
                for (int nt = 0; nt < 4; nt++)
                    mma_tf32(acc[mt][nt], af[mt], bf[nt]);
        }
        __syncthreads();
    }

    // epilogue
#pragma unroll
    for (int mt = 0; mt < 4; mt++) {
#pragma unroll
        for (int half = 0; half < 2; half++) {   // c0/c1 then c2/c3 (row +8)
            int m = bm + wm * 64 + mt * 16 + g + half * 8;
            int b = m >> 11;
            int s = m & 2047;
#pragma unroll
            for (int nt = 0; nt < 4; nt++) {
                int n = bn + wn * 32 + nt * 8 + 2 * t;
                float v0 = acc[mt][nt][half * 2 + 0] + __ldg(&bias[n]);
                float v1 = acc[mt][nt][half * 2 + 1] + __ldg(&bias[n + 1]);
                float* op;
                if (mode == 1) {
                    int h = n >> 6, d0 = n & 63;
                    op = out + (((size_t)b * HH + h) * SS + s) * DD + d0;
                } else {
                    op = out + (size_t)m * NN + n;
                }
                float2 v = make_float2(v0, v1);
                *(float2*)op = v;
            }
        }
    }
}

// ---------------------------------------------------------------------------
// prep kernels
// ---------------------------------------------------------------------------
__global__ void cvt_tf32_kernel(const float4* __restrict__ in, float4* __restrict__ outp, int n4)
{
    for (int i = blockIdx.x * blockDim.x + threadIdx.x; i < n4; i += gridDim.x * blockDim.x) {
        float4 v = in[i];
        v.x = tf32r(v.x); v.y = tf32r(v.y); v.z = tf32r(v.z); v.w = tf32r(v.w);
        outp[i] = v;
    }
}

// in fp32 [B][R][C] -> out fp32(tf32-rounded) [B*C][R]
__global__ void transpose_t32_kernel(const float* __restrict__ in, float* __restrict__ outp,
                                     int R, int C)
{
    __shared__ float tile[32][33];
    const int b = blockIdx.z;
    const int c0 = blockIdx.x * 32, r0 = blockIdx.y * 32;
    const int tx = threadIdx.x, ty = threadIdx.y;
    const float* inb = in + (size_t)b * R * C;
#pragma unroll
    for (int j = 0; j < 32; j += 8)
        tile[ty + j][tx] = inb[(size_t)(r0 + ty + j) * C + c0 + tx];
    __syncthreads();
    float* ob = outp + (size_t)b * C * R;
#pragma unroll
    for (int j = 0; j < 32; j += 8)
        ob[(size_t)(c0 + ty + j) * R + r0 + tx] = tf32r(tile[tx][ty + j]);
}

// ---------------------------------------------------------------------------
// Flash attention (causal), fp32, Br=Bc=64. Output tf32-rounded (feeds the
// tf32 projection GEMM).
// ---------------------------------------------------------------------------
#define FLDS 68

__global__ void __launch_bounds__(256) flash_kernel(
    const float* __restrict__ q, const float* __restrict__ k,
    const float* __restrict__ v, float* __restrict__ outp)
{
    extern __shared__ float sm[];
    float* Qs = sm;                 // [64][FLDS]
    float* KP = sm + 64 * FLDS;     // K tile then P tile
    float* Vt = sm + 2 * 64 * FLDS; // V transposed [d][t]

    const int qi = blockIdx.x;
    const int bh = blockIdx.y;
    const size_t base = (size_t)bh * SS * DD;
    const int tid = threadIdx.x;
    const int w = tid >> 5;
    const int l = tid & 31;
    const int r0 = w * 8;
    const int qr0 = qi * 64;

    for (int idx = tid; idx < 64 * 16; idx += 256) {
        int r = idx >> 4;
        int dq = (idx & 15) * 4;
        *(float4*)&Qs[r * FLDS + dq] = *(const float4*)(q + base + (size_t)(qr0 + r) * DD + dq);
    }

    float m_run[8], l_run[8], o[8][2];
#pragma unroll
    for (int i = 0; i < 8; i++) {
        m_run[i] = -1e30f; l_run[i] = 0.f; o[i][0] = 0.f; o[i][1] = 0.f;
    }

    const float sc = 0.125f * 1.4426950408889634f;

    for (int j = 0; j <= qi; ++j) {
        __syncthreads();
        for (int idx = tid; idx < 64 * 16; idx += 256) {
            int t = idx >> 4;
            int dq = (idx & 15) * 4;
            const float* kb = k + base + (size_t)(j * 64 + t) * DD + dq;
            *(float4*)&KP[t * FLDS + dq] = *(const float4*)kb;
            float4 vv = *(const float4*)(v + base + (size_t)(j * 64 + t) * DD + dq);
            Vt[(dq + 0) * FLDS + t] = vv.x;
            Vt[(dq + 1) * FLDS + t] = vv.y;
            Vt[(dq + 2) * FLDS + t] = vv.z;
            Vt[(dq + 3) * FLDS + t] = vv.w;
        }
        __syncthreads();

        float s[8][2];
#pragma unroll
        for (int i = 0; i < 8; i++) { s[i][0] = 0.f; s[i][1] = 0.f; }
#pragma unroll
        for (int d4 = 0; d4 < 64; d4 += 4) {
            float4 k0f = *(const float4*)&KP[l * FLDS + d4];
            float4 k1f = *(const float4*)&KP[(l + 32) * FLDS + d4];
#pragma unroll
            for (int i = 0; i < 8; i++) {
                float4 qf = *(const float4*)&Qs[(r0 + i) * FLDS + d4];
                s[i][0] += qf.x * k0f.x + qf.y * k0f.y + qf.z * k0f.z + qf.w * k0f.w;
                s[i][1] += qf.x * k1f.x + qf.y * k1f.y + qf.z * k1f.z + qf.w * k1f.w;
            }
        }

        const bool diag = (j == qi);
#pragma unroll
        for (int i = 0; i < 8; i++) {
            float s0 = s[i][0] * sc;
            float s1 = s[i][1] * sc;
            if (diag) {
                int R = r0 + i;
                if (l > R) s0 = -1e30f;
                if (l + 32 > R) s1 = -1e30f;
            }
            float mloc = fmaxf(s0, s1);
#pragma unroll
            for (int off = 16; off; off >>= 1)
                mloc = fmaxf(mloc, __shfl_xor_sync(0xffffffffu, mloc, off));
            float mn = fmaxf(m_run[i], mloc);
            float p0 = exp2f(s0 - mn);
            float p1 = exp2f(s1 - mn);
            float alpha = exp2f(m_run[i] - mn);
            float rs = p0 + p1;
#pragma unroll
            for (int off = 16; off; off >>= 1)
                rs += __shfl_xor_sync(0xffffffffu, rs, off);
            l_run[i] = l_run[i] * alpha + rs;
            m_run[i] = mn;
            o[i][0] *= alpha;
            o[i][1] *= alpha;
            s[i][0] = p0;
            s[i][1] = p1;
        }

        __syncthreads();
#pragma unroll
        for (int i = 0; i < 8; i++) {
            KP[(r0 + i) * FLDS + l]      = s[i][0];
            KP[(r0 + i) * FLDS + l + 32] = s[i][1];
        }
        __syncthreads();

#pragma unroll
        for (int t4 = 0; t4 < 64; t4 += 4) {
            float4 v0f = *(const float4*)&Vt[l * FLDS + t4];
            float4 v1f = *(const float4*)&Vt[(l + 32) * FLDS + t4];
#pragma unroll
            for (int i = 0; i < 8; i++) {
                float4 pf = *(const float4*)&KP[(r0 + i) * FLDS + t4];
                o[i][0] += pf.x * v0f.x + pf.y * v0f.y + pf.z * v0f.z + pf.w * v0f.w;
                o[i][1] += pf.x * v1f.x + pf.y * v1f.y + pf.z * v1f.z + pf.w * v1f.w;
            }
        }
    }

    const int b = bh >> 4;
    const int h = bh & 15;
#pragma unroll
    for (int i = 0; i < 8; i++) {
        int R = qr0 + r0 + i;
        float inv = 1.f / l_run[i];
        size_t ob = ((size_t)b * SS + R) * EE + h * 64;
        outp[ob + l]      = tf32r(o[i][0] * inv);
        outp[ob + l + 32] = tf32r(o[i][1] * inv);
    }
}

// ---------------------------------------------------------------------------
extern "C" void kernel_launch(void* const* d_in, const int* in_sizes, int n_in,
                              void* d_out, int out_size)
{
    const float* x  = (const float*)d_in[0];
    const float* Wq = (const float*)d_in[1];
    const float* bq = (const float*)d_in[2];
    const float* Wk = (const float*)d_in[3];
    const float* bk = (const float*)d_in[4];
    const float* Wv = (const float*)d_in[5];
    const float* bv = (const float*)d_in[6];
    const float* Wp = (const float*)d_in[7];
    const float* bp = (const float*)d_in[8];
    float* out = (float*)d_out;

    float *qp, *kp, *vp, *ap, *xap, *wtp;
    cudaGetSymbolAddress((void**)&qp, g_q);
    cudaGetSymbolAddress((void**)&kp, g_k);
    cudaGetSymbolAddress((void**)&vp, g_v);
    cudaGetSymbolAddress((void**)&ap, g_attn);
    cudaGetSymbolAddress((void**)&xap, g_xa);
    cudaGetSymbolAddress((void**)&wtp, g_wt);

    const int gemm_smem = GNSTG * GSTAGEB;   // 61440
    cudaFuncSetAttribute(tc_gemm_kernel, cudaFuncAttributeMaxDynamicSharedMemorySize, gemm_smem);
    const int fl_smem = 3 * 64 * FLDS * sizeof(float);
    cudaFuncSetAttribute(flash_kernel, cudaFuncAttributeMaxDynamicSharedMemorySize, fl_smem);

    // x -> tf32-rounded
    cvt_tf32_kernel<<<1024, 256>>>((const float4*)x, (float4*)xap, MM * KK / 4);

    dim3 gg(NN / 128, MM / 128);   // (8, 64)
    dim3 tb(32, 8);

    // Q
    transpose_t32_kernel<<<dim3(2, 32, 16), tb>>>(Wq, wtp, EE, DD);
    tc_gemm_kernel<<<gg, 256, gemm_smem>>>(xap, wtp, bq, qp, 1);
    // K
    transpose_t32_kernel<<<dim3(2, 32, 16), tb>>>(Wk, wtp, EE, DD);
    tc_gemm_kernel<<<gg, 256, gemm_smem>>>(xap, wtp, bk, kp, 1);
    // V
    transpose_t32_kernel<<<dim3(2, 32, 16), tb>>>(Wv, wtp, EE, DD);
    tc_gemm_kernel<<<gg, 256, gemm_smem>>>(xap, wtp, bv, vp, 1);

    // attention
    dim3 fg(SS / 64, BB * HH);     // (32, 64)
    flash_kernel<<<fg, 256, fl_smem>>>(qp, kp, vp, ap);

    // output projection
    transpose_t32_kernel<<<dim3(32, 32, 1), tb>>>(Wp, wtp, EE, EE);
    tc_gemm_kernel<<<gg, 256, gemm_smem>>>(ap, wtp, bp, out, 0);
}

// round 5
// speedup vs baseline: 2.3721x; 1.7122x over previous
#include <cuda_runtime.h>
#include <cuda_bf16.h>
#include <math.h>
#include <cstdint>

// Problem constants
#define BB 4
#define SS 2048
#define EE 1024
#define HH 16
#define DD 64
#define MM (BB * SS)   // 8192
#define NN 1024
#define KK 1024

// Scratch (device globals — no cudaMalloc allowed)
__device__ float g_q[BB * HH * SS * DD];    // [b][h][s][d]
__device__ float g_k[BB * HH * SS * DD];
__device__ float g_v[BB * HH * SS * DD];
__device__ float g_attn[MM * EE];           // [b][s][h*64+d], tf32-rounded
__device__ float g_xa[MM * KK];             // x, tf32-rounded
__device__ float g_wt[NN * KK];             // current weight, transposed [N][K], tf32-rounded

// ---------------------------------------------------------------------------
// helpers
// ---------------------------------------------------------------------------
__device__ __forceinline__ uint32_t smem_u32(const void* p) {
    uint32_t a;
    asm("{ .reg .u64 t; cvta.to.shared.u64 t, %1; cvt.u32.u64 %0, t; }" : "=r"(a) : "l"(p));
    return a;
}
__device__ __forceinline__ float tf32r(float x) {
    uint32_t y;
    asm("cvt.rna.tf32.f32 %0, %1;" : "=r"(y) : "f"(x));
    return __uint_as_float(y);
}
__device__ __forceinline__ float ex2(float x) {
    float y;
    asm("ex2.approx.ftz.f32 %0, %1;" : "=f"(y) : "f"(x));
    return y;
}
__device__ __forceinline__ uint32_t lds32(uint32_t a) {
    uint32_t v;
    asm volatile("ld.shared.b32 %0, [%1];" : "=r"(v) : "r"(a));
    return v;
}
__device__ __forceinline__ void cp16(uint32_t dst, const void* src) {
    asm volatile("cp.async.ca.shared.global [%0], [%1], 16;" :: "r"(dst), "l"(src));
}
__device__ __forceinline__ void mma_tf32(float* c, const uint32_t* a, const uint32_t* b) {
    asm volatile(
        "mma.sync.aligned.m16n8k8.row.col.f32.tf32.tf32.f32 "
        "{%0,%1,%2,%3}, {%4,%5,%6,%7}, {%8,%9}, {%0,%1,%2,%3};"
        : "+f"(c[0]), "+f"(c[1]), "+f"(c[2]), "+f"(c[3])
        : "r"(a[0]), "r"(a[1]), "r"(a[2]), "r"(a[3]), "r"(b[0]), "r"(b[1]));
}

// ---------------------------------------------------------------------------
// mma.sync TF32 GEMM: out[M,N] = A[M,K] * Bt[N,K]^T + bias
// BM=BN=128, BK=16, 256 threads (8 warps, 2x4 warp grid, 64x32 warp tile).
// cp.async 3-stage pipeline. smem row stride 20 floats (conflict-free).
// mode 1: out is [B,H,S,D] per-head, tf32-rounded;  mode 0: out row-major fp32
// ---------------------------------------------------------------------------
#define GROWB 80
#define GBUF (128 * GROWB)
#define GSTAGEB (2 * GBUF)
#define GNSTG 3
#define GNKS (KK / 16)

__global__ void __launch_bounds__(256) tc_gemm_kernel(
    const float* __restrict__ A, const float* __restrict__ Bt,
    const float* __restrict__ bias, float* __restrict__ out, int mode)
{
    extern __shared__ char smc[];
    const uint32_t dat_u = smem_u32(smc);

    const int tid = threadIdx.x;
    const int wid = tid >> 5;
    const int lane = tid & 31;
    const int g = lane >> 2;
    const int t = lane & 3;
    const int wm = wid >> 2;
    const int wn = wid & 3;
    const int bm = blockIdx.y * 128;
    const int bn = blockIdx.x * 128;
    const int c0 = tid * 2;

    float acc[4][4][4];
#pragma unroll
    for (int mt = 0; mt < 4; mt++)
#pragma unroll
        for (int nt = 0; nt < 4; nt++)
#pragma unroll
            for (int r = 0; r < 4; r++) acc[mt][nt][r] = 0.f;

#pragma unroll
    for (int s = 0; s < GNSTG - 1; ++s) {
        const uint32_t sb = dat_u + s * GSTAGEB;
        const int kof = s * 16;
#pragma unroll
        for (int i = 0; i < 2; ++i) {
            int c = c0 + i;
            int row = c >> 2, q = c & 3;
            cp16(sb + row * GROWB + q * 16, A + (size_t)(bm + row) * KK + kof + q * 4);
            cp16(sb + GBUF + row * GROWB + q * 16, Bt + (size_t)(bn + row) * KK + kof + q * 4);
        }
        asm volatile("cp.async.commit_group;" ::: "memory");
    }

    for (int ks = 0; ks < GNKS; ++ks) {
        const int ldk = ks + GNSTG - 1;
        if (ldk < GNKS) {
            const uint32_t sb = dat_u + (ldk % GNSTG) * GSTAGEB;
            const int kof = ldk * 16;
#pragma unroll
            for (int i = 0; i < 2; ++i) {
                int c = c0 + i;
                int row = c >> 2, q = c & 3;
                cp16(sb + row * GROWB + q * 16, A + (size_t)(bm + row) * KK + kof + q * 4);
                cp16(sb + GBUF + row * GROWB + q * 16, Bt + (size_t)(bn + row) * KK + kof + q * 4);
            }
        }
        asm volatile("cp.async.commit_group;" ::: "memory");
        asm volatile("cp.async.wait_group 2;" ::: "memory");
        __syncthreads();

        const uint32_t aB = dat_u + (ks % GNSTG) * GSTAGEB;
        const uint32_t bB = aB + GBUF;
#pragma unroll
        for (int k2 = 0; k2 < 2; ++k2) {
            uint32_t af[4][4], bf[4][2];
#pragma unroll
            for (int mt = 0; mt < 4; mt++) {
                int row = wm * 64 + mt * 16 + g;
                uint32_t a0 = aB + row * GROWB + (k2 * 8 + t) * 4;
                af[mt][0] = lds32(a0);
                af[mt][1] = lds32(a0 + 8 * GROWB);
                af[mt][2] = lds32(a0 + 16);
                af[mt][3] = lds32(a0 + 8 * GROWB + 16);
            }
#pragma unroll
            for (int nt = 0; nt < 4; nt++) {
                int nrow = wn * 32 + nt * 8 + g;
                uint32_t b0 = bB + nrow * GROWB + (k2 * 8 + t) * 4;
                bf[nt][0] = lds32(b0);
                bf[nt][1] = lds32(b0 + 16);
            }
#pragma unroll
            for (int mt = 0; mt < 4; mt++)
#pragma unroll
                for (int nt = 0; nt < 4; nt++)
                    mma_tf32(acc[mt][nt], af[mt], bf[nt]);
        }
        __syncthreads();
    }

#pragma unroll
    for (int mt = 0; mt < 4; mt++) {
#pragma unroll
        for (int half = 0; half < 2; half++) {
            int m = bm + wm * 64 + mt * 16 + g + half * 8;
            int b = m >> 11;
            int s = m & 2047;
#pragma unroll
            for (int nt = 0; nt < 4; nt++) {
                int n = bn + wn * 32 + nt * 8 + 2 * t;
                float v0 = acc[mt][nt][half * 2 + 0] + __ldg(&bias[n]);
                float v1 = acc[mt][nt][half * 2 + 1] + __ldg(&bias[n + 1]);
                float* op;
                if (mode == 1) {
                    int h = n >> 6, d0 = n & 63;
                    op = out + (((size_t)b * HH + h) * SS + s) * DD + d0;
                    v0 = tf32r(v0);   // q/k/v feed tf32 attention MMAs
                    v1 = tf32r(v1);
                } else {
                    op = out + (size_t)m * NN + n;
                }
                *(float2*)op = make_float2(v0, v1);
            }
        }
    }
}

// ---------------------------------------------------------------------------
// prep kernels
// ---------------------------------------------------------------------------
__global__ void cvt_tf32_kernel(const float4* __restrict__ in, float4* __restrict__ outp, int n4)
{
    for (int i = blockIdx.x * blockDim.x + threadIdx.x; i < n4; i += gridDim.x * blockDim.x) {
        float4 v = in[i];
        v.x = tf32r(v.x); v.y = tf32r(v.y); v.z = tf32r(v.z); v.w = tf32r(v.w);
        outp[i] = v;
    }
}

__global__ void transpose_t32_kernel(const float* __restrict__ in, float* __restrict__ outp,
                                     int R, int C)
{
    __shared__ float tile[32][33];
    const int b = blockIdx.z;
    const int c0 = blockIdx.x * 32, r0 = blockIdx.y * 32;
    const int tx = threadIdx.x, ty = threadIdx.y;
    const float* inb = in + (size_t)b * R * C;
#pragma unroll
    for (int j = 0; j < 32; j += 8)
        tile[ty + j][tx] = inb[(size_t)(r0 + ty + j) * C + c0 + tx];
    __syncthreads();
    float* ob = outp + (size_t)b * C * R;
#pragma unroll
    for (int j = 0; j < 32; j += 8)
        ob[(size_t)(c0 + ty + j) * R + r0 + tx] = tf32r(tile[tx][ty + j]);
}

// ---------------------------------------------------------------------------
// Flash attention (causal) via mma.sync tf32. Br=Bc=64, 128 threads (4 warps),
// warp w owns rows [w*16, w*16+16). Fragment-register softmax.
// smem: Qs/Ks/Vs/Ps each [64][FST], FST=68 floats -> fragment loads hit banks
// (4g+t) = conflict-free.
// ---------------------------------------------------------------------------
#define FST 68

__global__ void __launch_bounds__(128) flash_mma_kernel(
    const float* __restrict__ q, const float* __restrict__ k,
    const float* __restrict__ v, float* __restrict__ outp)
{
    extern __shared__ float sm[];
    const uint32_t smb = smem_u32(sm);
    const uint32_t QsB = smb;
    const uint32_t KsB = smb + 64 * FST * 4;
    const uint32_t VsB = smb + 2 * 64 * FST * 4;
    const uint32_t PsB = smb + 3 * 64 * FST * 4;
    float* Qs = sm;
    float* Ks = sm + 64 * FST;
    float* Vs = sm + 2 * 64 * FST;
    float* Ps = sm + 3 * 64 * FST;

    const int qi = blockIdx.x;
    const int bh = blockIdx.y;
    const size_t base = (size_t)bh * SS * DD;
    const int tid = threadIdx.x;
    const int w = tid >> 5;
    const int lane = tid & 31;
    const int g = lane >> 2;
    const int t = lane & 3;
    const int qr0 = qi * 64;
    const int r0g = w * 16 + g;          // local row of c0/c1; +8 for c2/c3

    // load Q tile
    for (int idx = tid; idx < 64 * 16; idx += 128) {
        int r = idx >> 4, dq = (idx & 15) * 4;
        *(float4*)&Qs[r * FST + dq] = *(const float4*)(q + base + (size_t)(qr0 + r) * DD + dq);
    }

    float o[8][4];
#pragma unroll
    for (int dt = 0; dt < 8; dt++)
#pragma unroll
        for (int r = 0; r < 4; r++) o[dt][r] = 0.f;
    float m0 = -1e30f, m1 = -1e30f, l0 = 0.f, l1 = 0.f;
    const float sc = 0.125f * 1.4426950408889634f;

    for (int j = 0; j <= qi; ++j) {
        __syncthreads();   // previous tile's Ks/Vs fully consumed
        for (int idx = tid; idx < 64 * 16; idx += 128) {
            int tt = idx >> 4, dq = (idx & 15) * 4;
            *(float4*)&Ks[tt * FST + dq] = *(const float4*)(k + base + (size_t)(j * 64 + tt) * DD + dq);
            *(float4*)&Vs[tt * FST + dq] = *(const float4*)(v + base + (size_t)(j * 64 + tt) * DD + dq);
        }
        __syncthreads();

        // ---- S = Q K^T (tf32 mma) ----
        float sa[8][4];
#pragma unroll
        for (int nt = 0; nt < 8; nt++)
#pragma unroll
            for (int r = 0; r < 4; r++) sa[nt][r] = 0.f;

#pragma unroll
        for (int ks = 0; ks < 8; ++ks) {
            uint32_t af[4];
            uint32_t a0 = QsB + (r0g * FST + ks * 8 + t) * 4;
            af[0] = lds32(a0);
            af[1] = lds32(a0 + 8 * FST * 4);
            af[2] = lds32(a0 + 16);
            af[3] = lds32(a0 + 8 * FST * 4 + 16);
#pragma unroll
            for (int nt = 0; nt < 8; nt++) {
                uint32_t b0 = KsB + ((nt * 8 + g) * FST + ks * 8 + t) * 4;
                uint32_t bf[2] = { lds32(b0), lds32(b0 + 16) };
                mma_tf32(sa[nt], af, bf);
            }
        }

        // ---- fragment softmax ----
        const bool diag = (j == qi);
        float mloc0 = -1e30f, mloc1 = -1e30f;
#pragma unroll
        for (int nt = 0; nt < 8; nt++) {
            sa[nt][0] *= sc; sa[nt][1] *= sc; sa[nt][2] *= sc; sa[nt][3] *= sc;
            if (diag) {
                int col = nt * 8 + 2 * t;
                if (col     > r0g)     sa[nt][0] = -1e30f;
                if (col + 1 > r0g)     sa[nt][1] = -1e30f;
                if (col     > r0g + 8) sa[nt][2] = -1e30f;
                if (col + 1 > r0g + 8) sa[nt][3] = -1e30f;
            }
            mloc0 = fmaxf(mloc0, fmaxf(sa[nt][0], sa[nt][1]));
            mloc1 = fmaxf(mloc1, fmaxf(sa[nt][2], sa[nt][3]));
        }
        mloc0 = fmaxf(mloc0, __shfl_xor_sync(0xffffffffu, mloc0, 1));
        mloc0 = fmaxf(mloc0, __shfl_xor_sync(0xffffffffu, mloc0, 2));
        mloc1 = fmaxf(mloc1, __shfl_xor_sync(0xffffffffu, mloc1, 1));
        mloc1 = fmaxf(mloc1, __shfl_xor_sync(0xffffffffu, mloc1, 2));

        float mn0 = fmaxf(m0, mloc0), mn1 = fmaxf(m1, mloc1);
        float al0 = ex2(m0 - mn0), al1 = ex2(m1 - mn1);
        float rs0 = 0.f, rs1 = 0.f;
#pragma unroll
        for (int nt = 0; nt < 8; nt++) {
            sa[nt][0] = ex2(sa[nt][0] - mn0);
            sa[nt][1] = ex2(sa[nt][1] - mn0);
            sa[nt][2] = ex2(sa[nt][2] - mn1);
            sa[nt][3] = ex2(sa[nt][3] - mn1);
            rs0 += sa[nt][0] + sa[nt][1];
            rs1 += sa[nt][2] + sa[nt][3];
        }
        rs0 += __shfl_xor_sync(0xffffffffu, rs0, 1);
        rs0 += __shfl_xor_sync(0xffffffffu, rs0, 2);
        rs1 += __shfl_xor_sync(0xffffffffu, rs1, 1);
        rs1 += __shfl_xor_sync(0xffffffffu, rs1, 2);
        l0 = l0 * al0 + rs0;
        l1 = l1 * al1 + rs1;
        m0 = mn0; m1 = mn1;
#pragma unroll
        for (int dt = 0; dt < 8; dt++) {
            o[dt][0] *= al0; o[dt][1] *= al0;
            o[dt][2] *= al1; o[dt][3] *= al1;
        }

        // stage P (C-layout -> smem); warp-private rows, so only __syncwarp
#pragma unroll
        for (int nt = 0; nt < 8; nt++) {
            *(float2*)&Ps[r0g * FST + nt * 8 + 2 * t]       = make_float2(sa[nt][0], sa[nt][1]);
            *(float2*)&Ps[(r0g + 8) * FST + nt * 8 + 2 * t] = make_float2(sa[nt][2], sa[nt][3]);
        }
        __syncwarp();

        // ---- O += P V (tf32 mma) ----
#pragma unroll
        for (int ks = 0; ks < 8; ++ks) {
            uint32_t af[4];
            uint32_t a0 = PsB + (r0g * FST + ks * 8 + t) * 4;
            af[0] = lds32(a0);
            af[1] = lds32(a0 + 8 * FST * 4);
            af[2] = lds32(a0 + 16);
            af[3] = lds32(a0 + 8 * FST * 4 + 16);
#pragma unroll
            for (int dt = 0; dt < 8; dt++) {
                uint32_t b0 = VsB + ((ks * 8 + t) * FST + dt * 8 + g) * 4;
                uint32_t bf[2] = { lds32(b0), lds32(b0 + 4 * FST * 4) };
                mma_tf32(o[dt], af, bf);
            }
        }
    }

    // epilogue
    const int b = bh >> 4;
    const int h = bh & 15;
    const float inv0 = 1.f / l0, inv1 = 1.f / l1;
    const int row0 = qr0 + r0g, row1 = row0 + 8;
#pragma unroll
    for (int nt = 0; nt < 8; nt++) {
        int d = nt * 8 + 2 * t;
        size_t ob0 = ((size_t)b * SS + row0) * EE + h * 64 + d;
        size_t ob1 = ((size_t)b * SS + row1) * EE + h * 64 + d;
        *(float2*)&outp[ob0] = make_float2(tf32r(o[nt][0] * inv0), tf32r(o[nt][1] * inv0));
        *(float2*)&outp[ob1] = make_float2(tf32r(o[nt][2] * inv1), tf32r(o[nt][3] * inv1));
    }
}

// ---------------------------------------------------------------------------
extern "C" void kernel_launch(void* const* d_in, const int* in_sizes, int n_in,
                              void* d_out, int out_size)
{
    const float* x  = (const float*)d_in[0];
    const float* Wq = (const float*)d_in[1];
    const float* bq = (const float*)d_in[2];
    const float* Wk = (const float*)d_in[3];
    const float* bk = (const float*)d_in[4];
    const float* Wv = (const float*)d_in[5];
    const float* bv = (const float*)d_in[6];
    const float* Wp = (const float*)d_in[7];
    const float* bp = (const float*)d_in[8];
    float* out = (float*)d_out;

    float *qp, *kp, *vp, *ap, *xap, *wtp;
    cudaGetSymbolAddress((void**)&qp, g_q);
    cudaGetSymbolAddress((void**)&kp, g_k);
    cudaGetSymbolAddress((void**)&vp, g_v);
    cudaGetSymbolAddress((void**)&ap, g_attn);
    cudaGetSymbolAddress((void**)&xap, g_xa);
    cudaGetSymbolAddress((void**)&wtp, g_wt);

    const int gemm_smem = GNSTG * GSTAGEB;
    cudaFuncSetAttribute(tc_gemm_kernel, cudaFuncAttributeMaxDynamicSharedMemorySize, gemm_smem);
    const int fl_smem = 4 * 64 * FST * sizeof(float);   // 69632
    cudaFuncSetAttribute(flash_mma_kernel, cudaFuncAttributeMaxDynamicSharedMemorySize, fl_smem);

    cvt_tf32_kernel<<<1024, 256>>>((const float4*)x, (float4*)xap, MM * KK / 4);

    dim3 gg(NN / 128, MM / 128);
    dim3 tb(32, 8);

    transpose_t32_kernel<<<dim3(2, 32, 16), tb>>>(Wq, wtp, EE, DD);
    tc_gemm_kernel<<<gg, 256, gemm_smem>>>(xap, wtp, bq, qp, 1);
    transpose_t32_kernel<<<dim3(2, 32, 16), tb>>>(Wk, wtp, EE, DD);
    tc_gemm_kernel<<<gg, 256, gemm_smem>>>(xap, wtp, bk, kp, 1);
    transpose_t32_kernel<<<dim3(2, 32, 16), tb>>>(Wv, wtp, EE, DD);
    tc_gemm_kernel<<<gg, 256, gemm_smem>>>(xap, wtp, bv, vp, 1);

    dim3 fg(SS / 64, BB * HH);
    flash_mma_kernel<<<fg, 128, fl_smem>>>(qp, kp, vp, ap);

    transpose_t32_kernel<<<dim3(32, 32, 1), tb>>>(Wp, wtp, EE, EE);
    tc_gemm_kernel<<<gg, 256, gemm_smem>>>(ap, wtp, bp, out, 0);
}

// round 6
// speedup vs baseline: 4.6776x; 1.9719x over previous
#include <cuda_runtime.h>
#include <cuda_fp16.h>
#include <math.h>
#include <cstdint>

// Problem constants
#define BB 4
#define SS 2048
#define EE 1024
#define HH 16
#define DD 64
#define MM (BB * SS)   // 8192
#define NN 1024
#define KK 1024

// Scratch (device globals — no cudaMalloc allowed)
__device__ __half g_q[BB * HH * SS * DD];    // [b][h][s][d]
__device__ __half g_k[BB * HH * SS * DD];    // [b][h][s][d]
__device__ __half g_v[BB * HH * SS * DD];    // TRANSPOSED: [b][h][d][s]
__device__ __half g_attn[MM * EE];           // [b][s][h*64+d]
__device__ __half g_xa[MM * KK];             // x as fp16
__device__ __half g_wt[NN * KK];             // weight transposed [N][K] fp16

// ---------------------------------------------------------------------------
// helpers
// ---------------------------------------------------------------------------
__device__ __forceinline__ uint32_t smem_u32(const void* p) {
    uint32_t a;
    asm("{ .reg .u64 t; cvta.to.shared.u64 t, %1; cvt.u32.u64 %0, t; }" : "=r"(a) : "l"(p));
    return a;
}
__device__ __forceinline__ float ex2(float x) {
    float y;
    asm("ex2.approx.ftz.f32 %0, %1;" : "=f"(y) : "f"(x));
    return y;
}
__device__ __forceinline__ uint32_t lds32(uint32_t a) {
    uint32_t v;
    asm volatile("ld.shared.b32 %0, [%1];" : "=r"(v) : "r"(a));
    return v;
}
__device__ __forceinline__ void sts32(uint32_t a, uint32_t v) {
    asm volatile("st.shared.b32 [%0], %1;" :: "r"(a), "r"(v));
}
__device__ __forceinline__ void cp16(uint32_t dst, const void* src) {
    asm volatile("cp.async.ca.shared.global [%0], [%1], 16;" :: "r"(dst), "l"(src));
}
// m16n8k16 fp16 with fp32 accumulate
__device__ __forceinline__ void mma_f16(float* c, const uint32_t* a, const uint32_t* b) {
    asm volatile(
        "mma.sync.aligned.m16n8k16.row.col.f32.f16.f16.f32 "
        "{%0,%1,%2,%3}, {%4,%5,%6,%7}, {%8,%9}, {%0,%1,%2,%3};"
        : "+f"(c[0]), "+f"(c[1]), "+f"(c[2]), "+f"(c[3])
        : "r"(a[0]), "r"(a[1]), "r"(a[2]), "r"(a[3]), "r"(b[0]), "r"(b[1]));
}

// ---------------------------------------------------------------------------
// fp16 mma.sync GEMM: out[M,N] = A[M,K] * Bt[N,K]^T + bias
// BM=BN=128, BK=32 halves (64B/row), 256 threads (8 warps, 2x4 grid, 64x32
// warp tile), cp.async 3-stage, one __syncthreads per stage.
// smem row = 20 words (80B): word addr (20g+t) % 32 distinct -> conflict-free.
// mode 0: out fp32 row-major [M,N]
// mode 1: out half [B][H][S][D]
// mode 2: out half [B][H][D][S]   (V transposed for flash)
// ---------------------------------------------------------------------------
#define GROWB 80
#define GBUF (128 * GROWB)      // 10240
#define GSTAGEB (2 * GBUF)      // 20480
#define GNSTG 3
#define GNKS (KK / 32)          // 32

__global__ void __launch_bounds__(256) tc_gemm_kernel(
    const __half* __restrict__ A, const __half* __restrict__ Bt,
    const float* __restrict__ bias, void* __restrict__ outv, int mode)
{
    extern __shared__ char smc[];
    const uint32_t dat_u = smem_u32(smc);

    const int tid = threadIdx.x;
    const int wid = tid >> 5;
    const int lane = tid & 31;
    const int g = lane >> 2;
    const int t = lane & 3;
    const int wm = wid >> 2;
    const int wn = wid & 3;
    const int bm = blockIdx.y * 128;
    const int bn = blockIdx.x * 128;
    const int c0 = tid * 2;

    float acc[4][4][4];
#pragma unroll
    for (int mt = 0; mt < 4; mt++)
#pragma unroll
        for (int nt = 0; nt < 4; nt++)
#pragma unroll
            for (int r = 0; r < 4; r++) acc[mt][nt][r] = 0.f;

    // prologue: stages 0,1
#pragma unroll
    for (int s = 0; s < GNSTG - 1; ++s) {
        const uint32_t sb = dat_u + s * GSTAGEB;
        const int kof = s * 32;
#pragma unroll
        for (int i = 0; i < 2; ++i) {
            int c = c0 + i;
            int row = c >> 2, q = c & 3;
            cp16(sb + row * GROWB + q * 16, A + (size_t)(bm + row) * KK + kof + q * 8);
            cp16(sb + GBUF + row * GROWB + q * 16, Bt + (size_t)(bn + row) * KK + kof + q * 8);
        }
        asm volatile("cp.async.commit_group;" ::: "memory");
    }

    for (int ks = 0; ks < GNKS; ++ks) {
        asm volatile("cp.async.wait_group 1;" ::: "memory");
        __syncthreads();
        const int ldk = ks + GNSTG - 1;
        if (ldk < GNKS) {
            const uint32_t sb = dat_u + (ldk % GNSTG) * GSTAGEB;
            const int kof = ldk * 32;
#pragma unroll
            for (int i = 0; i < 2; ++i) {
                int c = c0 + i;
                int row = c >> 2, q = c & 3;
                cp16(sb + row * GROWB + q * 16, A + (size_t)(bm + row) * KK + kof + q * 8);
                cp16(sb + GBUF + row * GROWB + q * 16, Bt + (size_t)(bn + row) * KK + kof + q * 8);
            }
            asm volatile("cp.async.commit_group;" ::: "memory");
        }

        const uint32_t aB = dat_u + (ks % GNSTG) * GSTAGEB;
        const uint32_t bB = aB + GBUF;
#pragma unroll
        for (int k2 = 0; k2 < 2; ++k2) {   // two k16 steps in BK=32
            uint32_t af[4][4], bf[4][2];
#pragma unroll
            for (int mt = 0; mt < 4; mt++) {
                int row = wm * 64 + mt * 16 + g;
                uint32_t a0 = aB + row * GROWB + (k2 * 8 + t) * 4;
                af[mt][0] = lds32(a0);
                af[mt][1] = lds32(a0 + 8 * GROWB);
                af[mt][2] = lds32(a0 + 16);
                af[mt][3] = lds32(a0 + 8 * GROWB + 16);
            }
#pragma unroll
            for (int nt = 0; nt < 4; nt++) {
                int nrow = wn * 32 + nt * 8 + g;
                uint32_t b0 = bB + nrow * GROWB + (k2 * 8 + t) * 4;
                bf[nt][0] = lds32(b0);
                bf[nt][1] = lds32(b0 + 16);
            }
#pragma unroll
            for (int mt = 0; mt < 4; mt++)
#pragma unroll
                for (int nt = 0; nt < 4; nt++)
                    mma_f16(acc[mt][nt], af[mt], bf[nt]);
        }
    }

    // epilogue
#pragma unroll
    for (int mt = 0; mt < 4; mt++) {
#pragma unroll
        for (int half_ = 0; half_ < 2; half_++) {
            int m = bm + wm * 64 + mt * 16 + g + half_ * 8;
            int b = m >> 11;
            int s = m & 2047;
#pragma unroll
            for (int nt = 0; nt < 4; nt++) {
                int n = bn + wn * 32 + nt * 8 + 2 * t;
                float v0 = acc[mt][nt][half_ * 2 + 0] + __ldg(&bias[n]);
                float v1 = acc[mt][nt][half_ * 2 + 1] + __ldg(&bias[n + 1]);
                if (mode == 0) {
                    float* op = (float*)outv + (size_t)m * NN + n;
                    *(float2*)op = make_float2(v0, v1);
                } else {
                    int h = n >> 6, d0 = n & 63;
                    __half* ob = (__half*)outv;
                    if (mode == 1) {
                        __half* op = ob + (((size_t)b * HH + h) * SS + s) * DD + d0;
                        *(__half2*)op = __floats2half2_rn(v0, v1);
                    } else {  // mode 2: [b][h][d][s]
                        size_t bhd = (((size_t)b * HH + h) * DD + d0) * SS + s;
                        ob[bhd] = __float2half_rn(v0);
                        ob[bhd + SS] = __float2half_rn(v1);
                    }
                }
            }
        }
    }
}

// ---------------------------------------------------------------------------
// prep kernels
// ---------------------------------------------------------------------------
__global__ void cvt_half_kernel(const float4* __restrict__ in, __half2* __restrict__ outp, int n4)
{
    for (int i = blockIdx.x * blockDim.x + threadIdx.x; i < n4; i += gridDim.x * blockDim.x) {
        float4 v = in[i];
        outp[2 * i]     = __floats2half2_rn(v.x, v.y);
        outp[2 * i + 1] = __floats2half2_rn(v.z, v.w);
    }
}

// in fp32 [b][R][C] -> out half [b][C][R]
__global__ void transpose_h_kernel(const float* __restrict__ in, __half* __restrict__ outp,
                                   int R, int C)
{
    __shared__ float tile[32][33];
    const int b = blockIdx.z;
    const int c0 = blockIdx.x * 32, r0 = blockIdx.y * 32;
    const int tx = threadIdx.x, ty = threadIdx.y;
    const float* inb = in + (size_t)b * R * C;
#pragma unroll
    for (int j = 0; j < 32; j += 8)
        tile[ty + j][tx] = inb[(size_t)(r0 + ty + j) * C + c0 + tx];
    __syncthreads();
    __half* ob = outp + (size_t)b * C * R;
#pragma unroll
    for (int j = 0; j < 32; j += 8)
        ob[(size_t)(c0 + ty + j) * R + r0 + tx] = __float2half_rn(tile[tx][ty + j]);
}

// ---------------------------------------------------------------------------
// Flash attention (causal) via fp16 mma.sync. Br=Bc=64, 128 threads (4 warps),
// warp w owns rows [w*16, w*16+16). K/Vt tiles double-buffered via cp.async,
// one __syncthreads per j-tile. Fragment-register softmax.
// smem rows: 32 data words (64 halves) + 4 pad -> stride 36 words (144B).
// Fragment lds banks: (4g + t) -> conflict-free.
// ---------------------------------------------------------------------------
#define FSTW 36
#define FROWB (FSTW * 4)        // 144
#define FTILE (64 * FROWB)      // 9216

__global__ void __launch_bounds__(128) flash_mma_kernel(
    const __half* __restrict__ q, const __half* __restrict__ k,
    const __half* __restrict__ vt, __half* __restrict__ outp)
{
    extern __shared__ char smc[];
    const uint32_t smb = smem_u32(smc);
    const uint32_t QsB = smb;
    const uint32_t PsB = smb + FTILE;
    // per buffer: K tile then Vt tile
    const uint32_t KB0 = smb + 2 * FTILE;

    const int qi = blockIdx.x;
    const int bh = blockIdx.y;
    const size_t base = (size_t)bh * SS * DD;   // same stride for k and vt
    const int tid = threadIdx.x;
    const int w = tid >> 5;
    const int lane = tid & 31;
    const int g = lane >> 2;
    const int t = lane & 3;
    const int qr0 = qi * 64;
    const int r0g = w * 16 + g;

    // load Q tile (plain vector loads; first in-loop sync covers visibility)
    for (int idx = tid; idx < 64 * 8; idx += 128) {
        int r = idx >> 3, qc = idx & 7;
        *(uint4*)(smc + (QsB - smb) + r * FROWB + qc * 16) =
            *(const uint4*)(q + base + (size_t)(qr0 + r) * DD + qc * 8);
    }

    // prologue: prefetch K/Vt tile j=0 into buffer 0
    {
        const uint32_t kb = KB0, vb = KB0 + FTILE;
        for (int idx = tid; idx < 128 * 8; idx += 128) {
            int m = idx >> 3, qc = idx & 7;
            if (m < 64)
                cp16(kb + m * FROWB + qc * 16, k + base + (size_t)m * DD + qc * 8);
            else
                cp16(vb + (m - 64) * FROWB + qc * 16, vt + base + (size_t)(m - 64) * SS + qc * 8);
        }
        asm volatile("cp.async.commit_group;" ::: "memory");
    }

    float o[8][4];
#pragma unroll
    for (int dt = 0; dt < 8; dt++)
#pragma unroll
        for (int r = 0; r < 4; r++) o[dt][r] = 0.f;
    float m0 = -1e30f, m1 = -1e30f, l0 = 0.f, l1 = 0.f;
    const float sc = 0.125f * 1.4426950408889634f;

    for (int j = 0; j <= qi; ++j) {
        asm volatile("cp.async.wait_group 0;" ::: "memory");
        __syncthreads();
        const uint32_t kb = KB0 + (j & 1) * 2 * FTILE;
        const uint32_t vb = kb + FTILE;

        // prefetch next tile into the other buffer (overlaps compute)
        if (j < qi) {
            const uint32_t kb2 = KB0 + ((j + 1) & 1) * 2 * FTILE;
            const uint32_t vb2 = kb2 + FTILE;
            const size_t koff = base + (size_t)(j + 1) * 64 * DD;
            const size_t voff = base + (size_t)(j + 1) * 64;
            for (int idx = tid; idx < 128 * 8; idx += 128) {
                int m = idx >> 3, qc = idx & 7;
                if (m < 64)
                    cp16(kb2 + m * FROWB + qc * 16, k + koff + (size_t)m * DD + qc * 8);
                else
                    cp16(vb2 + (m - 64) * FROWB + qc * 16, vt + voff + (size_t)(m - 64) * SS + qc * 8);
            }
            asm volatile("cp.async.commit_group;" ::: "memory");
        }

        // ---- S = Q K^T ----
        float sa[8][4];
#pragma unroll
        for (int nt = 0; nt < 8; nt++)
#pragma unroll
            for (int r = 0; r < 4; r++) sa[nt][r] = 0.f;

#pragma unroll
        for (int ks = 0; ks < 4; ++ks) {   // 4 x k16 over D=64
            uint32_t af[4];
            uint32_t a0 = QsB + r0g * FROWB + (ks * 8 + t) * 4;
            af[0] = lds32(a0);
            af[1] = lds32(a0 + 8 * FROWB);
            af[2] = lds32(a0 + 16);
            af[3] = lds32(a0 + 8 * FROWB + 16);
#pragma unroll
            for (int nt = 0; nt < 8; nt++) {
                uint32_t b0 = kb + (nt * 8 + g) * FROWB + (ks * 8 + t) * 4;
                uint32_t bf[2] = { lds32(b0), lds32(b0 + 16) };
                mma_f16(sa[nt], af, bf);
            }
        }

        // ---- fragment softmax ----
        const bool diag = (j == qi);
        float mloc0 = -1e30f, mloc1 = -1e30f;
#pragma unroll
        for (int nt = 0; nt < 8; nt++) {
            sa[nt][0] *= sc; sa[nt][1] *= sc; sa[nt][2] *= sc; sa[nt][3] *= sc;
            if (diag) {
                int col = nt * 8 + 2 * t;
                if (col     > r0g)     sa[nt][0] = -1e30f;
                if (col + 1 > r0g)     sa[nt][1] = -1e30f;
                if (col     > r0g + 8) sa[nt][2] = -1e30f;
                if (col + 1 > r0g + 8) sa[nt][3] = -1e30f;
            }
            mloc0 = fmaxf(mloc0, fmaxf(sa[nt][0], sa[nt][1]));
            mloc1 = fmaxf(mloc1, fmaxf(sa[nt][2], sa[nt][3]));
        }
        mloc0 = fmaxf(mloc0, __shfl_xor_sync(0xffffffffu, mloc0, 1));
        mloc0 = fmaxf(mloc0, __shfl_xor_sync(0xffffffffu, mloc0, 2));
        mloc1 = fmaxf(mloc1, __shfl_xor_sync(0xffffffffu, mloc1, 1));
        mloc1 = fmaxf(mloc1, __shfl_xor_sync(0xffffffffu, mloc1, 2));

        float mn0 = fmaxf(m0, mloc0), mn1 = fmaxf(m1, mloc1);
        float al0 = ex2(m0 - mn0), al1 = ex2(m1 - mn1);
        float rs0 = 0.f, rs1 = 0.f;
#pragma unroll
        for (int nt = 0; nt < 8; nt++) {
            sa[nt][0] = ex2(sa[nt][0] - mn0);
            sa[nt][1] = ex2(sa[nt][1] - mn0);
            sa[nt][2] = ex2(sa[nt][2] - mn1);
            sa[nt][3] = ex2(sa[nt][3] - mn1);
            rs0 += sa[nt][0] + sa[nt][1];
            rs1 += sa[nt][2] + sa[nt][3];
        }
        rs0 += __shfl_xor_sync(0xffffffffu, rs0, 1);
        rs0 += __shfl_xor_sync(0xffffffffu, rs0, 2);
        rs1 += __shfl_xor_sync(0xffffffffu, rs1, 1);
        rs1 += __shfl_xor_sync(0xffffffffu, rs1, 2);
        l0 = l0 * al0 + rs0;
        l1 = l1 * al1 + rs1;
        m0 = mn0; m1 = mn1;
#pragma unroll
        for (int dt = 0; dt < 8; dt++) {
            o[dt][0] *= al0; o[dt][1] *= al0;
            o[dt][2] *= al1; o[dt][3] *= al1;
        }

        // stage P as fp16 (warp-private rows, __syncwarp only)
#pragma unroll
        for (int nt = 0; nt < 8; nt++) {
            uint32_t p0, p1;
            __half2 h0 = __floats2half2_rn(sa[nt][0], sa[nt][1]);
            __half2 h1 = __floats2half2_rn(sa[nt][2], sa[nt][3]);
            p0 = *(uint32_t*)&h0;
            p1 = *(uint32_t*)&h1;
            sts32(PsB + r0g * FROWB + (nt * 4 + t) * 4, p0);
            sts32(PsB + (r0g + 8) * FROWB + (nt * 4 + t) * 4, p1);
        }
        __syncwarp();

        // ---- O += P V  (B from Vt[d][t]) ----
#pragma unroll
        for (int ks = 0; ks < 4; ++ks) {   // 4 x k16 over T=64
            uint32_t af[4];
            uint32_t a0 = PsB + r0g * FROWB + (ks * 8 + t) * 4;
            af[0] = lds32(a0);
            af[1] = lds32(a0 + 8 * FROWB);
            af[2] = lds32(a0 + 16);
            af[3] = lds32(a0 + 8 * FROWB + 16);
#pragma unroll
            for (int dt = 0; dt < 8; dt++) {
                uint32_t b0 = vb + (dt * 8 + g) * FROWB + (ks * 8 + t) * 4;
                uint32_t bf[2] = { lds32(b0), lds32(b0 + 16) };
                mma_f16(o[dt], af, bf);
            }
        }
    }

    // epilogue: normalize, write half to [B, S, H*D]
    const int b = bh >> 4;
    const int h = bh & 15;
    const float inv0 = 1.f / l0, inv1 = 1.f / l1;
    const int row0 = qr0 + r0g, row1 = row0 + 8;
#pragma unroll
    for (int nt = 0; nt < 8; nt++) {
        int d = nt * 8 + 2 * t;
        size_t ob0 = ((size_t)b * SS + row0) * EE + h * 64 + d;
        size_t ob1 = ((size_t)b * SS + row1) * EE + h * 64 + d;
        *(__half2*)&outp[ob0] = __floats2half2_rn(o[nt][0] * inv0, o[nt][1] * inv0);
        *(__half2*)&outp[ob1] = __floats2half2_rn(o[nt][2] * inv1, o[nt][3] * inv1);
    }
}

// ---------------------------------------------------------------------------
extern "C" void kernel_launch(void* const* d_in, const int* in_sizes, int n_in,
                              void* d_out, int out_size)
{
    const float* x  = (const float*)d_in[0];
    const float* Wq = (const float*)d_in[1];
    const float* bq = (const float*)d_in[2];
    const float* Wk = (const float*)d_in[3];
    const float* bk = (const float*)d_in[4];
    const float* Wv = (const float*)d_in[5];
    const float* bv = (const float*)d_in[6];
    const float* Wp = (const float*)d_in[7];
    const float* bp = (const float*)d_in[8];
    float* out = (float*)d_out;

    __half *qp, *kp, *vp, *ap, *xap, *wtp;
    cudaGetSymbolAddress((void**)&qp, g_q);
    cudaGetSymbolAddress((void**)&kp, g_k);
    cudaGetSymbolAddress((void**)&vp, g_v);
    cudaGetSymbolAddress((void**)&ap, g_attn);
    cudaGetSymbolAddress((void**)&xap, g_xa);
    cudaGetSymbolAddress((void**)&wtp, g_wt);

    const int gemm_smem = GNSTG * GSTAGEB;                 // 61440
    cudaFuncSetAttribute(tc_gemm_kernel, cudaFuncAttributeMaxDynamicSharedMemorySize, gemm_smem);
    const int fl_smem = 2 * FTILE + 4 * FTILE;             // Q + Ps + 2x(K+Vt) = 55296
    cudaFuncSetAttribute(flash_mma_kernel, cudaFuncAttributeMaxDynamicSharedMemorySize, fl_smem);

    cvt_half_kernel<<<1024, 256>>>((const float4*)x, (__half2*)xap, MM * KK / 4);

    dim3 gg(NN / 128, MM / 128);
    dim3 tb(32, 8);

    transpose_h_kernel<<<dim3(2, 32, 16), tb>>>(Wq, wtp, EE, DD);
    tc_gemm_kernel<<<gg, 256, gemm_smem>>>(xap, wtp, bq, qp, 1);
    transpose_h_kernel<<<dim3(2, 32, 16), tb>>>(Wk, wtp, EE, DD);
    tc_gemm_kernel<<<gg, 256, gemm_smem>>>(xap, wtp, bk, kp, 1);
    transpose_h_kernel<<<dim3(2, 32, 16), tb>>>(Wv, wtp, EE, DD);
    tc_gemm_kernel<<<gg, 256, gemm_smem>>>(xap, wtp, bv, vp, 2);

    dim3 fg(SS / 64, BB * HH);
    flash_mma_kernel<<<fg, 128, fl_smem>>>(qp, kp, vp, ap);

    transpose_h_kernel<<<dim3(32, 32, 1), tb>>>(Wp, wtp, EE, EE);
    tc_gemm_kernel<<<gg, 256, gemm_smem>>>(ap, wtp, bp, out, 0);
}

// round 8
// speedup vs baseline: 5.7511x; 1.2295x over previous
#include <cuda_runtime.h>
#include <cuda_fp16.h>
#include <math.h>
#include <cstdint>

// Problem constants
#define BB 4
#define SS 2048
#define EE 1024
#define HH 16
#define DD 64
#define MM (BB * SS)   // 8192
#define NN 1024
#define KK 1024

// Scratch (device globals — no cudaMalloc allowed)
__device__ __half g_q[BB * HH * SS * DD];    // [b][h][s][d]
__device__ __half g_k[BB * HH * SS * DD];    // [b][h][s][d]
__device__ __half g_v[BB * HH * SS * DD];    // TRANSPOSED: [b][h][d][s]
__device__ __half g_attn[MM * EE];           // [b][s][h*64+d]
__device__ __half g_xa[MM * KK];             // x as fp16
__device__ __half g_wt3[3 * NN * KK];        // Wq|Wk|Wv transposed [3N][K] fp16
__device__ __half g_wt[NN * KK];             // Wp transposed [N][K] fp16

// ---------------------------------------------------------------------------
// helpers
// ---------------------------------------------------------------------------
__device__ __forceinline__ uint32_t smem_u32(const void* p) {
    uint32_t a;
    asm("{ .reg .u64 t; cvta.to.shared.u64 t, %1; cvt.u32.u64 %0, t; }" : "=r"(a) : "l"(p));
    return a;
}
__device__ __forceinline__ float ex2(float x) {
    float y;
    asm("ex2.approx.ftz.f32 %0, %1;" : "=f"(y) : "f"(x));
    return y;
}
__device__ __forceinline__ void cp16(uint32_t dst, const void* src) {
    asm volatile("cp.async.ca.shared.global [%0], [%1], 16;" :: "r"(dst), "l"(src));
}
__device__ __forceinline__ void ldm4(uint32_t* r, uint32_t addr) {
    asm volatile("ldmatrix.sync.aligned.m8n8.x4.shared.b16 {%0,%1,%2,%3}, [%4];"
                 : "=r"(r[0]), "=r"(r[1]), "=r"(r[2]), "=r"(r[3]) : "r"(addr));
}
__device__ __forceinline__ void mma_f16(float* c, const uint32_t* a, const uint32_t* b) {
    asm volatile(
        "mma.sync.aligned.m16n8k16.row.col.f32.f16.f16.f32 "
        "{%0,%1,%2,%3}, {%4,%5,%6,%7}, {%8,%9}, {%0,%1,%2,%3};"
        : "+f"(c[0]), "+f"(c[1]), "+f"(c[2]), "+f"(c[3])
        : "r"(a[0]), "r"(a[1]), "r"(a[2]), "r"(a[3]), "r"(b[0]), "r"(b[1]));
}
__device__ __forceinline__ uint32_t packh2(float a, float b) {
    __half2 h = __floats2half2_rn(a, b);
    return *(uint32_t*)&h;
}

// ---------------------------------------------------------------------------
// fp16 mma.sync GEMM. BM=BN=128, BK=32 halves, 256 threads (2x4 warps,
// 64x32 warp tile), cp.async 4-stage (commit EVERY iter — group-FIFO
// correctness), ldmatrix fragment loads. smem row = 80B (bank-conflict-free
// for both st and ldmatrix: (5r+c)%8 distinct).
// MODE 0: out fp32 row-major [M,NN], bias=b0
// MODE 1: fused QKV, Ncols=3072: n>>10 selects {Q,K,V}; Q,K half [B][H][S][D],
//         V half [B][H][D][S]; biases b0,b1,b2
// ---------------------------------------------------------------------------
#define GROWB 80
#define GBUF (128 * GROWB)      // 10240
#define GSTAGEB (2 * GBUF)      // 20480
#define GNSTG 4
#define GNKS (KK / 32)          // 32

template <int MODE>
__global__ void __launch_bounds__(256) tc_gemm_kernel(
    const __half* __restrict__ A, const __half* __restrict__ Bt,
    const float* __restrict__ b0, const float* __restrict__ b1,
    const float* __restrict__ b2,
    void* __restrict__ o0, __half* __restrict__ o1, __half* __restrict__ o2)
{
    extern __shared__ char smc[];
    const uint32_t dat_u = smem_u32(smc);

    const int tid = threadIdx.x;
    const int wid = tid >> 5;
    const int lane = tid & 31;
    const int g = lane >> 2;
    const int t = lane & 3;
    const int wm = wid >> 2;
    const int wn = wid & 3;
    const int bm = blockIdx.y * 128;
    const int bn = blockIdx.x * 128;
    const int c0 = tid * 2;

    // ldmatrix per-lane static offsets
    const uint32_t aoff = (uint32_t)((wm * 64 + (lane & 15)) * GROWB + ((lane >> 4) << 4));
    const uint32_t boff = (uint32_t)((wn * 32 + ((lane >> 4) << 3) + (lane & 7)) * GROWB
                                     + (((lane >> 3) & 1) << 4));

    float acc[4][4][4];
#pragma unroll
    for (int mt = 0; mt < 4; mt++)
#pragma unroll
        for (int nt = 0; nt < 4; nt++)
#pragma unroll
            for (int r = 0; r < 4; r++) acc[mt][nt][r] = 0.f;

    // prologue: stages 0..GNSTG-2
#pragma unroll
    for (int s = 0; s < GNSTG - 1; ++s) {
        const uint32_t sb = dat_u + s * GSTAGEB;
        const int kof = s * 32;
#pragma unroll
        for (int i = 0; i < 2; ++i) {
            int c = c0 + i;
            int row = c >> 2, q = c & 3;
            cp16(sb + row * GROWB + q * 16, A + (size_t)(bm + row) * KK + kof + q * 8);
            cp16(sb + GBUF + row * GROWB + q * 16, Bt + (size_t)(bn + row) * KK + kof + q * 8);
        }
        asm volatile("cp.async.commit_group;" ::: "memory");
    }

    for (int ks = 0; ks < GNKS; ++ks) {
        asm volatile("cp.async.wait_group %0;" :: "n"(GNSTG - 2) : "memory");
        __syncthreads();
        const int ldk = ks + GNSTG - 1;
        if (ldk < GNKS) {
            const uint32_t sb = dat_u + (ldk & (GNSTG - 1)) * GSTAGEB;
            const int kof = ldk * 32;
#pragma unroll
            for (int i = 0; i < 2; ++i) {
                int c = c0 + i;
                int row = c >> 2, q = c & 3;
                cp16(sb + row * GROWB + q * 16, A + (size_t)(bm + row) * KK + kof + q * 8);
                cp16(sb + GBUF + row * GROWB + q * 16, Bt + (size_t)(bn + row) * KK + kof + q * 8);
            }
        }
        asm volatile("cp.async.commit_group;" ::: "memory");   // ALWAYS (FIFO count)

        const uint32_t aB = dat_u + (ks & (GNSTG - 1)) * GSTAGEB;
        const uint32_t bB = aB + GBUF;
#pragma unroll
        for (int k2 = 0; k2 < 2; ++k2) {
            uint32_t af[4][4], bf[2][4];
#pragma unroll
            for (int mt = 0; mt < 4; mt++)
                ldm4(af[mt], aB + aoff + mt * (16 * GROWB) + k2 * 32);
#pragma unroll
            for (int p = 0; p < 2; p++)
                ldm4(bf[p], bB + boff + p * (16 * GROWB) + k2 * 32);
#pragma unroll
            for (int mt = 0; mt < 4; mt++)
#pragma unroll
                for (int p = 0; p < 2; p++) {
                    mma_f16(acc[mt][2 * p],     af[mt], bf[p] + 0);
                    mma_f16(acc[mt][2 * p + 1], af[mt], bf[p] + 2);
                }
        }
    }

    // epilogue
#pragma unroll
    for (int mt = 0; mt < 4; mt++) {
#pragma unroll
        for (int half_ = 0; half_ < 2; half_++) {
            int m = bm + wm * 64 + mt * 16 + g + half_ * 8;
            int b = m >> 11;
            int s = m & 2047;
#pragma unroll
            for (int nt = 0; nt < 4; nt++) {
                int n = bn + wn * 32 + nt * 8 + 2 * t;
                float v0 = acc[mt][nt][half_ * 2 + 0];
                float v1 = acc[mt][nt][half_ * 2 + 1];
                if (MODE == 0) {
                    v0 += __ldg(&b0[n]); v1 += __ldg(&b0[n + 1]);
                    float* op = (float*)o0 + (size_t)m * NN + n;
                    *(float2*)op = make_float2(v0, v1);
                } else {
                    int which = n >> 10;
                    int nh = n & 1023;
                    int h = nh >> 6, d0 = nh & 63;
                    const float* bptr = which == 0 ? b0 : (which == 1 ? b1 : b2);
                    v0 += __ldg(&bptr[nh]); v1 += __ldg(&bptr[nh + 1]);
                    if (which == 2) {   // V transposed [b][h][d][s]
                        size_t bhd = (((size_t)b * HH + h) * DD + d0) * SS + s;
                        o2[bhd] = __float2half_rn(v0);
                        o2[bhd + SS] = __float2half_rn(v1);
                    } else {
                        __half* dst = which == 0 ? (__half*)o0 : o1;
                        __half* op = dst + (((size_t)b * HH + h) * SS + s) * DD + d0;
                        *(__half2*)op = __floats2half2_rn(v0, v1);
                    }
                }
            }
        }
    }
}

// ---------------------------------------------------------------------------
// prep kernels
// ---------------------------------------------------------------------------
__global__ void cvt_half_kernel(const float4* __restrict__ in, __half2* __restrict__ outp, int n4)
{
    for (int i = blockIdx.x * blockDim.x + threadIdx.x; i < n4; i += gridDim.x * blockDim.x) {
        float4 v = in[i];
        outp[2 * i]     = __floats2half2_rn(v.x, v.y);
        outp[2 * i + 1] = __floats2half2_rn(v.z, v.w);
    }
}

// in fp32 [b][R][C] -> out half [b][C][R]
__global__ void transpose_h_kernel(const float* __restrict__ in, __half* __restrict__ outp,
                                   int R, int C)
{
    __shared__ float tile[32][33];
    const int b = blockIdx.z;
    const int c0 = blockIdx.x * 32, r0 = blockIdx.y * 32;
    const int tx = threadIdx.x, ty = threadIdx.y;
    const float* inb = in + (size_t)b * R * C;
#pragma unroll
    for (int j = 0; j < 32; j += 8)
        tile[ty + j][tx] = inb[(size_t)(r0 + ty + j) * C + c0 + tx];
    __syncthreads();
    __half* ob = outp + (size_t)b * C * R;
#pragma unroll
    for (int j = 0; j < 32; j += 8)
        ob[(size_t)(c0 + ty + j) * R + r0 + tx] = __float2half_rn(tile[tx][ty + j]);
}

// ---------------------------------------------------------------------------
// Flash attention (causal) fp16 mma. Br=Bc=64, 128 threads (4 warps, 16 rows
// each). Q fragments hoisted to registers; score C-fragments reused directly
// as PV A-fragments (no P smem round-trip). K/Vt double-buffered cp.async.
// smem rows 144B (9x16B): ldmatrix bankgroup (r+c)%8 distinct.
// ---------------------------------------------------------------------------
#define FROWB 144
#define FTILE (64 * FROWB)      // 9216

__global__ void __launch_bounds__(128) flash_mma_kernel(
    const __half* __restrict__ q, const __half* __restrict__ k,
    const __half* __restrict__ vt, __half* __restrict__ outp)
{
    extern __shared__ char smc[];
    const uint32_t smb = smem_u32(smc);
    const uint32_t QsB = smb;
    const uint32_t KB0 = smb + FTILE;    // buffers: [K|Vt] x2

    const int qi = blockIdx.x;
    const int bh = blockIdx.y;
    const size_t base = (size_t)bh * SS * DD;
    const int tid = threadIdx.x;
    const int w = tid >> 5;
    const int lane = tid & 31;
    const int g = lane >> 2;
    const int t = lane & 3;
    const int qr0 = qi * 64;
    const int r0g = w * 16 + g;

    const uint32_t qoff = (uint32_t)((w * 16 + (lane & 15)) * FROWB + ((lane >> 4) << 4));
    const uint32_t kvoff = (uint32_t)(((((lane >> 4) << 3) + (lane & 7)) * FROWB)
                                      + (((lane >> 3) & 1) << 4));

    // load Q tile
    for (int idx = tid; idx < 64 * 8; idx += 128) {
        int r = idx >> 3, qc = idx & 7;
        *(uint4*)(smc + r * FROWB + qc * 16) =
            *(const uint4*)(q + base + (size_t)(qr0 + r) * DD + qc * 8);
    }

    // prefetch K/Vt tile j=0 into buffer 0
    {
        const uint32_t kb = KB0, vb = KB0 + FTILE;
        for (int idx = tid; idx < 128 * 8; idx += 128) {
            int m = idx >> 3, qc = idx & 7;
            if (m < 64)
                cp16(kb + m * FROWB + qc * 16, k + base + (size_t)m * DD + qc * 8);
            else
                cp16(vb + (m - 64) * FROWB + qc * 16, vt + base + (size_t)(m - 64) * SS + qc * 8);
        }
        asm volatile("cp.async.commit_group;" ::: "memory");
    }
    __syncthreads();   // Q visible to all warps

    // hoist Q fragments (constant over j)
    uint32_t qf[4][4];
#pragma unroll
    for (int ks = 0; ks < 4; ks++) ldm4(qf[ks], QsB + qoff + ks * 32);

    float o[8][4];
#pragma unroll
    for (int dt = 0; dt < 8; dt++)
#pragma unroll
        for (int r = 0; r < 4; r++) o[dt][r] = 0.f;
    float m0 = -1e30f, m1 = -1e30f, l0 = 0.f, l1 = 0.f;
    const float sc = 0.125f * 1.4426950408889634f;

    for (int j = 0; j <= qi; ++j) {
        asm volatile("cp.async.wait_group 0;" ::: "memory");
        __syncthreads();
        const uint32_t kb = KB0 + (j & 1) * 2 * FTILE;
        const uint32_t vb = kb + FTILE;

        if (j < qi) {   // prefetch next tile (overlaps compute)
            const uint32_t kb2 = KB0 + ((j + 1) & 1) * 2 * FTILE;
            const uint32_t vb2 = kb2 + FTILE;
            const size_t koff = base + (size_t)(j + 1) * 64 * DD;
            const size_t voff = base + (size_t)(j + 1) * 64;
            for (int idx = tid; idx < 128 * 8; idx += 128) {
                int m = idx >> 3, qc = idx & 7;
                if (m < 64)
                    cp16(kb2 + m * FROWB + qc * 16, k + koff + (size_t)m * DD + qc * 8);
                else
                    cp16(vb2 + (m - 64) * FROWB + qc * 16, vt + voff + (size_t)(m - 64) * SS + qc * 8);
            }
            asm volatile("cp.async.commit_group;" ::: "memory");
        }

        // ---- S = Q K^T ----
        float sa[8][4];
#pragma unroll
        for (int nt = 0; nt < 8; nt++)
#pragma unroll
            for (int r = 0; r < 4; r++) sa[nt][r] = 0.f;
#pragma unroll
        for (int ks = 0; ks < 4; ++ks) {
#pragma unroll
            for (int p = 0; p < 4; p++) {
                uint32_t kf[4];
                ldm4(kf, kb + kvoff + p * (16 * FROWB) + ks * 32);
                mma_f16(sa[2 * p],     qf[ks], kf + 0);
                mma_f16(sa[2 * p + 1], qf[ks], kf + 2);
            }
        }

        // ---- fragment softmax ----
        const bool diag = (j == qi);
        float mloc0 = -1e30f, mloc1 = -1e30f;
#pragma unroll
        for (int nt = 0; nt < 8; nt++) {
            sa[nt][0] *= sc; sa[nt][1] *= sc; sa[nt][2] *= sc; sa[nt][3] *= sc;
            if (diag) {
                int col = nt * 8 + 2 * t;
                if (col     > r0g)     sa[nt][0] = -1e30f;
                if (col + 1 > r0g)     sa[nt][1] = -1e30f;
                if (col     > r0g + 8) sa[nt][2] = -1e30f;
                if (col + 1 > r0g + 8) sa[nt][3] = -1e30f;
            }
            mloc0 = fmaxf(mloc0, fmaxf(sa[nt][0], sa[nt][1]));
            mloc1 = fmaxf(mloc1, fmaxf(sa[nt][2], sa[nt][3]));
        }
        mloc0 = fmaxf(mloc0, __shfl_xor_sync(0xffffffffu, mloc0, 1));
        mloc0 = fmaxf(mloc0, __shfl_xor_sync(0xffffffffu, mloc0, 2));
        mloc1 = fmaxf(mloc1, __shfl_xor_sync(0xffffffffu, mloc1, 1));
        mloc1 = fmaxf(mloc1, __shfl_xor_sync(0xffffffffu, mloc1, 2));

        float mn0 = fmaxf(m0, mloc0), mn1 = fmaxf(m1, mloc1);
        float al0 = ex2(m0 - mn0), al1 = ex2(m1 - mn1);
        float rs0 = 0.f, rs1 = 0.f;
#pragma unroll
        for (int nt = 0; nt < 8; nt++) {
            sa[nt][0] = ex2(sa[nt][0] - mn0);
            sa[nt][1] = ex2(sa[nt][1] - mn0);
            sa[nt][2] = ex2(sa[nt][2] - mn1);
            sa[nt][3] = ex2(sa[nt][3] - mn1);
            rs0 += sa[nt][0] + sa[nt][1];
            rs1 += sa[nt][2] + sa[nt][3];
        }
        rs0 += __shfl_xor_sync(0xffffffffu, rs0, 1);
        rs0 += __shfl_xor_sync(0xffffffffu, rs0, 2);
        rs1 += __shfl_xor_sync(0xffffffffu, rs1, 1);
        rs1 += __shfl_xor_sync(0xffffffffu, rs1, 2);
        l0 = l0 * al0 + rs0;
        l1 = l1 * al1 + rs1;
        m0 = mn0; m1 = mn1;
#pragma unroll
        for (int dt = 0; dt < 8; dt++) {
            o[dt][0] *= al0; o[dt][1] *= al0;
            o[dt][2] *= al1; o[dt][3] *= al1;
        }

        // ---- O += P V : score C-frag (tiles 2ks,2ks+1) IS the A-frag ----
#pragma unroll
        for (int ks = 0; ks < 4; ++ks) {
            uint32_t pf[4];
            pf[0] = packh2(sa[2 * ks][0],     sa[2 * ks][1]);
            pf[1] = packh2(sa[2 * ks][2],     sa[2 * ks][3]);
            pf[2] = packh2(sa[2 * ks + 1][0], sa[2 * ks + 1][1]);
            pf[3] = packh2(sa[2 * ks + 1][2], sa[2 * ks + 1][3]);
#pragma unroll
            for (int p = 0; p < 4; p++) {
                uint32_t vf[4];
                ldm4(vf, vb + kvoff + p * (16 * FROWB) + ks * 32);
                mma_f16(o[2 * p],     pf, vf + 0);
                mma_f16(o[2 * p + 1], pf, vf + 2);
            }
        }
    }

    // epilogue: normalize, write half to [B, S, H*D]
    const int b = bh >> 4;
    const int h = bh & 15;
    const float inv0 = 1.f / l0, inv1 = 1.f / l1;
    const int row0 = qr0 + r0g, row1 = row0 + 8;
#pragma unroll
    for (int nt = 0; nt < 8; nt++) {
        int d = nt * 8 + 2 * t;
        size_t ob0 = ((size_t)b * SS + row0) * EE + h * 64 + d;
        size_t ob1 = ((size_t)b * SS + row1) * EE + h * 64 + d;
        *(__half2*)&outp[ob0] = __floats2half2_rn(o[nt][0] * inv0, o[nt][1] * inv0);
        *(__half2*)&outp[ob1] = __floats2half2_rn(o[nt][2] * inv1, o[nt][3] * inv1);
    }
}

// ---------------------------------------------------------------------------
extern "C" void kernel_launch(void* const* d_in, const int* in_sizes, int n_in,
                              void* d_out, int out_size)
{
    const float* x  = (const float*)d_in[0];
    const float* Wq = (const float*)d_in[1];
    const float* bq = (const float*)d_in[2];
    const float* Wk = (const float*)d_in[3];
    const float* bk = (const float*)d_in[4];
    const float* Wv = (const float*)d_in[5];
    const float* bv = (const float*)d_in[6];
    const float* Wp = (const float*)d_in[7];
    const float* bp = (const float*)d_in[8];
    float* out = (float*)d_out;

    __half *qp, *kp, *vp, *ap, *xap, *wtp, *wt3p;
    cudaGetSymbolAddress((void**)&qp, g_q);
    cudaGetSymbolAddress((void**)&kp, g_k);
    cudaGetSymbolAddress((void**)&vp, g_v);
    cudaGetSymbolAddress((void**)&ap, g_attn);
    cudaGetSymbolAddress((void**)&xap, g_xa);
    cudaGetSymbolAddress((void**)&wtp, g_wt);
    cudaGetSymbolAddress((void**)&wt3p, g_wt3);

    const int gemm_smem = GNSTG * GSTAGEB;                 // 81920
    cudaFuncSetAttribute(tc_gemm_kernel<0>, cudaFuncAttributeMaxDynamicSharedMemorySize, gemm_smem);
    cudaFuncSetAttribute(tc_gemm_kernel<1>, cudaFuncAttributeMaxDynamicSharedMemorySize, gemm_smem);
    const int fl_smem = 5 * FTILE;                         // 46080
    cudaFuncSetAttribute(flash_mma_kernel, cudaFuncAttributeMaxDynamicSharedMemorySize, fl_smem);

    cvt_half_kernel<<<1024, 256>>>((const float4*)x, (__half2*)xap, MM * KK / 4);

    dim3 tb(32, 8);
    transpose_h_kernel<<<dim3(2, 32, 16), tb>>>(Wq, wt3p, EE, DD);
    transpose_h_kernel<<<dim3(2, 32, 16), tb>>>(Wk, wt3p + NN * KK, EE, DD);
    transpose_h_kernel<<<dim3(2, 32, 16), tb>>>(Wv, wt3p + 2 * NN * KK, EE, DD);
    transpose_h_kernel<<<dim3(32, 32, 1), tb>>>(Wp, wtp, EE, EE);

    // fused QKV: N = 3072
    tc_gemm_kernel<1><<<dim3(24, 64), 256, gemm_smem>>>(
        xap, wt3p, bq, bk, bv, qp, kp, vp);

    dim3 fg(SS / 64, BB * HH);
    flash_mma_kernel<<<fg, 128, fl_smem>>>(qp, kp, vp, ap);

    // output projection
    tc_gemm_kernel<0><<<dim3(8, 64), 256, gemm_smem>>>(
        ap, wtp, bp, bp, bp, out, nullptr, nullptr);
}